// round 12
// baseline (speedup 1.0000x reference)
#include <cuda_runtime.h>
#include <cstdint>
#include <math.h>

#define NB     32
#define NEMB   256
#define NFEAT  512
#define NU     1024
#define NV     32000
#define NSTEPS 128

// ---------------- device state ----------------
__device__ float g_feat[NB * NFEAT];
__device__ float g_h[2][NB * NU];
__device__ float g_c[NB * NU];
__device__ int   g_tok[NB];
__device__ unsigned long long g_best[2][NB];
__device__ uint2 g_subkey[NSTEPS];

__device__ __forceinline__ float finz(float v) { return isfinite(v) ? v : 0.0f; }

// ---------------- threefry2x32-20 core ----------------
__device__ __forceinline__ uint32_t rotl32(uint32_t x, int r) {
    return (x << r) | (x >> (32 - r));
}

__device__ __forceinline__ void tf2x32(uint32_t k0, uint32_t k1,
                                       uint32_t x0, uint32_t x1,
                                       uint32_t& o0, uint32_t& o1) {
    uint32_t ks2 = k0 ^ k1 ^ 0x1BD11BDAu;
    x0 += k0; x1 += k1;
#define TFR(r) { x0 += x1; x1 = rotl32(x1, r); x1 ^= x0; }
    TFR(13) TFR(15) TFR(26) TFR(6)   x0 += k1;  x1 += ks2 + 1u;
    TFR(17) TFR(29) TFR(16) TFR(24)  x0 += ks2; x1 += k0 + 2u;
    TFR(13) TFR(15) TFR(26) TFR(6)   x0 += k0;  x1 += k1 + 3u;
    TFR(17) TFR(29) TFR(16) TFR(24)  x0 += k1;  x1 += ks2 + 4u;
    TFR(13) TFR(15) TFR(26) TFR(6)   x0 += ks2; x1 += k0 + 5u;
#undef TFR
    o0 = x0; o1 = x1;
}

// CONFIRMED (R11 probe): partitionable bits = o0^o1 of tf(key, (0, i))
__device__ __forceinline__ uint32_t jax_bits(uint2 key, uint32_t i) {
    uint32_t o0, o1;
    tf2x32(key.x, key.y, 0u, i, o0, o1);
    return o0 ^ o1;
}

// jax uniform->gumbel: u = max(tiny, bits->[1,2)-1); g = -log(-log(u))
__device__ __forceinline__ float gumbel_from_bits(uint32_t bits) {
    float f = __uint_as_float((bits >> 9) | 0x3f800000u) - 1.0f;
    float u = fmaxf(f, 1.1754944e-38f);
    return -logf(-logf(u));
}

// order-preserving pack, tie -> lowest index, NaN guarded
__device__ __forceinline__ unsigned long long pack_cand(float v, int idx) {
    if (!isfinite(v)) v = -3.402823466e38f;
    uint32_t b = __float_as_uint(v);
    b = (b & 0x80000000u) ? ~b : (b | 0x80000000u);
    return ((unsigned long long)b << 32) | (uint32_t)(~(uint32_t)idx);
}

// ---------------- init: zero state, build foldlike key chain ----------------
__global__ void init_kernel() {
    int tid = threadIdx.x;
    for (int i = tid; i < NB * NU; i += 256) {
        g_h[0][i] = 0.0f;
        g_h[1][i] = 0.0f;
        g_c[i] = 0.0f;
    }
    if (tid < 64) g_best[tid >> 5][tid & 31] = 0ULL;
    if (tid == 0) {
        // key = jax.random.key(42) -> (0, 42); foldlike split:
        // row r = tf(key, (0, r)); keys[0] -> next key, keys[1] -> sub
        uint32_t k0 = 0u, k1 = 42u;
        for (int s = 0; s < NSTEPS; s++) {
            uint32_t s0, s1, n0, n1;
            tf2x32(k0, k1, 0u, 1u, s0, s1);
            g_subkey[s] = make_uint2(s0, s1);
            tf2x32(k0, k1, 0u, 0u, n0, n1);
            k0 = n0; k1 = n1;
        }
    }
}

// ---------------- image feature mean ----------------
__global__ void feat_kernel(const float* __restrict__ img) {
    int idx = blockIdx.x * 256 + threadIdx.x;
    int b = idx >> 9;
    int c = idx & 511;
    float sum = 0.0f;
    const float* p = img + (size_t)b * 200 * NFEAT + c;
    for (int t = 0; t < 200; t++) sum += finz(p[t * NFEAT]);
    g_feat[idx] = finz(sum / 200.0f);
}

// ---------------- LSTM step ----------------
__global__ void lstm_kernel(const float* __restrict__ emb,
                            const float* __restrict__ Kw,
                            const float* __restrict__ Rw,
                            const float* __restrict__ bias,
                            int s) {
    __shared__ float xh[32][65];
    __shared__ int stok[32];
    int tid = threadIdx.x;
    if (tid < 32) {
        int t = (s == 0) ? 1 : g_tok[tid];
        if (t < 0 || t >= NV) t = 0;
        stok[tid] = t;
    }
    int b  = tid & 31;
    int jl = tid >> 5;
    int j  = (blockIdx.x << 3) + jl;
    int ph = s & 1;
    const float* hp = g_h[ph];
    float a0 = 0.f, a1 = 0.f, a2 = 0.f, a3 = 0.f;
    __syncthreads();

    for (int kt = 0; kt < 28; kt++) {
        __syncthreads();
        {
            int bb  = tid >> 3;
            int k0l = (tid & 7) << 3;
#pragma unroll
            for (int q = 0; q < 8; q++) {
                int kk = k0l + q;
                int k  = (kt << 6) + kk;
                float v;
                if (k < 256)       v = emb[stok[bb] * NEMB + k];
                else if (k < 768)  v = g_feat[bb * NFEAT + (k - 256)];
                else               v = hp[bb * NU + (k - 768)];
                xh[bb][kk] = finz(v);
            }
        }
        __syncthreads();
        const float* wbase = (kt < 12) ? (Kw + (size_t)(kt << 6) * 4096)
                                       : (Rw + (size_t)((kt - 12) << 6) * 4096);
#pragma unroll 4
        for (int kk = 0; kk < 64; kk++) {
            const float* wr = wbase + (size_t)kk * 4096;
            float xv = xh[b][kk];
            a0 += xv * wr[j];
            a1 += xv * wr[NU + j];
            a2 += xv * wr[2 * NU + j];
            a3 += xv * wr[3 * NU + j];
        }
    }
    a0 = finz(a0 + bias[j]);
    a1 = finz(a1 + bias[NU + j]);
    a2 = finz(a2 + bias[2 * NU + j]);
    a3 = finz(a3 + bias[3 * NU + j]);

    float ig = 1.0f / (1.0f + expf(-a0));
    float fg = 1.0f / (1.0f + expf(-a1));
    float og = 1.0f / (1.0f + expf(-a3));
    float cold = g_c[b * NU + j];
    float cn = finz(fg * cold + ig * tanhf(a2));
    float hn = finz(og * tanhf(cn));
    g_c[b * NU + j] = cn;
    g_h[ph ^ 1][b * NU + j] = hn;
}

// ---------------- logits + gumbel + argmax ----------------
__global__ void logits_kernel(const float* __restrict__ W,
                              const float* __restrict__ pb,
                              int s) {
    __shared__ float ht[128][36];
    int tid = threadIdx.x;
    int v = blockIdx.x * 256 + tid;
    int hpar = (s & 1) ^ 1;
    const float* h = g_h[hpar];

    float acc[NB];
#pragma unroll
    for (int b = 0; b < NB; b++) acc[b] = 0.0f;

    for (int ut = 0; ut < 8; ut++) {
        __syncthreads();
#pragma unroll
        for (int t = 0; t < 16; t++) {
            int idx = t * 256 + tid;
            int ul = idx & 127;
            int bb = idx >> 7;
            ht[ul][bb] = finz(h[bb * NU + ut * 128 + ul]);
        }
        __syncthreads();
        const float* wcol = W + (size_t)(ut * 128) * NV + v;
#pragma unroll 8
        for (int ul = 0; ul < 128; ul++) {
            float w = __ldg(wcol + (size_t)ul * NV);
#pragma unroll
            for (int q = 0; q < 8; q++) {
                float4 hq = *reinterpret_cast<const float4*>(&ht[ul][4 * q]);
                acc[4 * q + 0] += hq.x * w;
                acc[4 * q + 1] += hq.y * w;
                acc[4 * q + 2] += hq.z * w;
                acc[4 * q + 3] += hq.w * w;
            }
        }
    }

    float pbv = finz(pb[v]);
    uint2 sk = g_subkey[s];
    int lane = tid & 31;
    int par = s & 1;
#pragma unroll 1
    for (int b = 0; b < NB; b++) {
        uint32_t i = (uint32_t)(b * NV + v);
        float g = gumbel_from_bits(jax_bits(sk, i));
        float val = finz(acc[b]) + pbv + g;
        unsigned long long pk = pack_cand(val, v);
#pragma unroll
        for (int off = 16; off > 0; off >>= 1) {
            unsigned long long o = __shfl_down_sync(0xffffffffu, pk, off);
            if (o > pk) pk = o;
        }
        if (lane == 0) atomicMax(&g_best[par][b], pk);
    }
}

// ---------------- finalize step: FLOAT32 output ----------------
__global__ void fin_kernel(float* __restrict__ out, int s) {
    int b = threadIdx.x;
    if (b < NB) {
        unsigned long long p = g_best[s & 1][b];
        int v = (int)(~(unsigned int)p);
        out[b * NSTEPS + s] = (float)v;     // tokens < 2^24: exact in fp32
        g_tok[b] = v;
        g_best[(s & 1) ^ 1][b] = 0ULL;
    }
}

// ---------------- launch ----------------
extern "C" void kernel_launch(void* const* d_in, const int* in_sizes, int n_in,
                              void* d_out, int out_size) {
    // Size-convention detect via proj_b, strict per-mode binding.
    bool el_mode = false, byte_mode = false;
    for (int i = 0; i < n_in; i++) {
        if (in_sizes[i] == 32000)  el_mode   = true;
        if (in_sizes[i] == 128000) byte_mode = true;
    }
    const float* img  = (const float*)d_in[0];
    const float* emb  = (const float*)d_in[1];
    const float* Kw   = (const float*)d_in[2];
    const float* Rw   = (const float*)d_in[3];
    const float* bias = (const float*)d_in[4];
    const float* W    = (const float*)d_in[5];
    const float* pb   = (const float*)d_in[6];
    if (el_mode) {
        for (int i = 0; i < n_in; i++) {
            const float* p = (const float*)d_in[i];
            switch (in_sizes[i]) {
                case 3276800:  img  = p; break;
                case 8192000:  emb  = p; break;
                case 3145728:  Kw   = p; break;
                case 4194304:  Rw   = p; break;
                case 4096:     bias = p; break;
                case 32768000: W    = p; break;
                case 32000:    pb   = p; break;
                default: break;
            }
        }
    } else if (byte_mode) {
        for (int i = 0; i < n_in; i++) {
            const float* p = (const float*)d_in[i];
            switch (in_sizes[i]) {
                case 13107200:  img  = p; break;
                case 32768000:  emb  = p; break;
                case 12582912:  Kw   = p; break;
                case 16777216:  Rw   = p; break;
                case 16384:     bias = p; break;
                case 131072000: W    = p; break;
                case 128000:    pb   = p; break;
                default: break;
            }
        }
    }
    float* out = (float*)d_out;   // __output__ dtype: float32

    init_kernel<<<1, 256>>>();
    feat_kernel<<<64, 256>>>(img);
    for (int s = 0; s < NSTEPS; s++) {
        lstm_kernel<<<128, 256>>>(emb, Kw, Rw, bias, s);
        logits_kernel<<<125, 256>>>(W, pb, s);
        fin_kernel<<<1, 32>>>(out, s);
    }
}

// round 14
// speedup vs baseline: 6.1346x; 6.1346x over previous
#include <cuda_runtime.h>
#include <cstdint>
#include <math.h>

#define NB     32
#define NEMB   256
#define NFEAT  512
#define NU     1024
#define NV     32000
#define NSTEPS 128
#define KTOT   1792              // 256 emb + 512 feat + 1024 h
#define KCH    224               // K per chunk (8 chunks)
#define NJ     4096              // 4 gates x 1024

// ---------------- device state ----------------
__device__ float g_feat[NB * NFEAT];
__device__ float g_h[2][NB * NU];
__device__ float g_c[NB * NU];
__device__ int   g_tok[NB];
__device__ unsigned long long g_best[2][NB];
__device__ uint2 g_subkey[NSTEPS];
__device__ float g_zpart[8 * NB * NJ];     // split-K partials, 4 MB

// ---------------- threefry2x32-20 core ----------------
__device__ __forceinline__ uint32_t rotl32(uint32_t x, int r) {
    return (x << r) | (x >> (32 - r));
}

__device__ __forceinline__ void tf2x32(uint32_t k0, uint32_t k1,
                                       uint32_t x0, uint32_t x1,
                                       uint32_t& o0, uint32_t& o1) {
    uint32_t ks2 = k0 ^ k1 ^ 0x1BD11BDAu;
    x0 += k0; x1 += k1;
#define TFR(r) { x0 += x1; x1 = rotl32(x1, r); x1 ^= x0; }
    TFR(13) TFR(15) TFR(26) TFR(6)   x0 += k1;  x1 += ks2 + 1u;
    TFR(17) TFR(29) TFR(16) TFR(24)  x0 += ks2; x1 += k0 + 2u;
    TFR(13) TFR(15) TFR(26) TFR(6)   x0 += k0;  x1 += k1 + 3u;
    TFR(17) TFR(29) TFR(16) TFR(24)  x0 += k1;  x1 += ks2 + 4u;
    TFR(13) TFR(15) TFR(26) TFR(6)   x0 += ks2; x1 += k0 + 5u;
#undef TFR
    o0 = x0; o1 = x1;
}

// CONFIRMED: partitionable bits = o0^o1 of tf(key, (0, i))
__device__ __forceinline__ uint32_t jax_bits(uint2 key, uint32_t i) {
    uint32_t o0, o1;
    tf2x32(key.x, key.y, 0u, i, o0, o1);
    return o0 ^ o1;
}

__device__ __forceinline__ float gumbel_from_bits(uint32_t bits) {
    float f = __uint_as_float((bits >> 9) | 0x3f800000u) - 1.0f;
    float u = fmaxf(f, 1.1754944e-38f);
    return -logf(-logf(u));
}

__device__ __forceinline__ unsigned long long pack_cand(float v, int idx) {
    uint32_t b = __float_as_uint(v);
    b = (b & 0x80000000u) ? ~b : (b | 0x80000000u);
    return ((unsigned long long)b << 32) | (uint32_t)(~(uint32_t)idx);
}

// ---------------- init ----------------
__global__ void init_kernel() {
    int tid = threadIdx.x;
    for (int i = tid; i < NB * NU; i += 256) {
        g_h[0][i] = 0.0f;
        g_h[1][i] = 0.0f;
        g_c[i] = 0.0f;
    }
    if (tid < 64) g_best[tid >> 5][tid & 31] = 0ULL;
    if (tid == 0) {
        uint32_t k0 = 0u, k1 = 42u;   // jax.random.key(42)
        for (int s = 0; s < NSTEPS; s++) {
            uint32_t s0, s1, n0, n1;
            tf2x32(k0, k1, 0u, 1u, s0, s1);
            g_subkey[s] = make_uint2(s0, s1);
            tf2x32(k0, k1, 0u, 0u, n0, n1);
            k0 = n0; k1 = n1;
        }
    }
}

// ---------------- image feature mean ----------------
__global__ void feat_kernel(const float* __restrict__ img) {
    int idx = blockIdx.x * 256 + threadIdx.x;
    int b = idx >> 9;
    int c = idx & 511;
    float sum = 0.0f;
    const float* p = img + (size_t)b * 200 * NFEAT + c;
    for (int t = 0; t < 200; t++) sum += p[t * NFEAT];
    g_feat[idx] = sum / 200.0f;
}

// ---------------- LSTM split-K partial GEMM ----------------
// grid (16, 8): x = J-block (256 cols), y = K-chunk (224 rows).
// Thread owns one J column, 32 batch accumulators.
__global__ void __launch_bounds__(256, 2)
lstm_part_kernel(const float* __restrict__ emb,
                 const float* __restrict__ Kw,
                 const float* __restrict__ Rw,
                 int s) {
    __shared__ float xs[KCH][36];     // [k][b], row stride 36 (16B aligned)
    __shared__ int stok[NB];
    int tid = threadIdx.x;
    int J  = blockIdx.x * 256 + tid;
    int kc = blockIdx.y;
    int k0 = kc * KCH;

    if (tid < NB) {
        int t = (s == 0) ? 1 : g_tok[tid];
        if (t < 0 || t >= NV) t = 0;
        stok[tid] = t;
    }
    __syncthreads();
    const float* hp = g_h[s & 1];
    for (int i = tid; i < KCH * NB; i += 256) {
        int kl = i % KCH;
        int bb = i / KCH;
        int k = k0 + kl;
        float v;
        if (k < 256)      v = emb[stok[bb] * NEMB + k];
        else if (k < 768) v = g_feat[bb * NFEAT + (k - 256)];
        else              v = hp[bb * NU + (k - 768)];
        xs[kl][bb] = v;
    }
    __syncthreads();

    float acc[NB];
#pragma unroll
    for (int b = 0; b < NB; b++) acc[b] = 0.0f;

#pragma unroll 4
    for (int kl = 0; kl < KCH; kl++) {
        int k = k0 + kl;
        const float* wr = (k < 768) ? (Kw + (size_t)k * NJ)
                                    : (Rw + (size_t)(k - 768) * NJ);
        float w = __ldg(wr + J);
#pragma unroll
        for (int q = 0; q < 8; q++) {
            float4 xq = *reinterpret_cast<const float4*>(&xs[kl][4 * q]);
            acc[4 * q + 0] += xq.x * w;
            acc[4 * q + 1] += xq.y * w;
            acc[4 * q + 2] += xq.z * w;
            acc[4 * q + 3] += xq.w * w;
        }
    }

    float* zp = g_zpart + (size_t)kc * NB * NJ + J;
#pragma unroll
    for (int b = 0; b < NB; b++) zp[b * NJ] = acc[b];
}

// ---------------- LSTM combine: sum partials, gates, state update ----------
__global__ void lstm_combine_kernel(const float* __restrict__ bias, int s) {
    int idx = blockIdx.x * 256 + threadIdx.x;   // 0..32767
    int b = idx >> 10;
    int j = idx & 1023;
    float z0 = bias[j], z1 = bias[NU + j], z2 = bias[2 * NU + j], z3 = bias[3 * NU + j];
#pragma unroll
    for (int kc = 0; kc < 8; kc++) {
        const float* zp = g_zpart + (size_t)kc * NB * NJ + b * NJ;
        z0 += zp[j];
        z1 += zp[NU + j];
        z2 += zp[2 * NU + j];
        z3 += zp[3 * NU + j];
    }
    float ig = 1.0f / (1.0f + expf(-z0));
    float fg = 1.0f / (1.0f + expf(-z1));
    float og = 1.0f / (1.0f + expf(-z3));
    float cold = g_c[b * NU + j];
    float cn = fg * cold + ig * tanhf(z2);
    float hn = og * tanhf(cn);
    g_c[b * NU + j] = cn;
    g_h[(s & 1) ^ 1][b * NU + j] = hn;
}

// ---------------- logits + gumbel + argmax ----------------
// grid 250 x 256: block covers 128 v; thread = (vl = tid&127, kh = tid>>7).
// kh halves split the u-dimension (512 each), combined via smem at the end.
__global__ void __launch_bounds__(256, 2)
logits_kernel(const float* __restrict__ W,
              const float* __restrict__ pb,
              int s) {
    __shared__ float ht[256][36];     // staged h rows [u-local][b]
    int tid = threadIdx.x;
    int vl = tid & 127;
    int kh = tid >> 7;                // 0: u 0..511, 1: u 512..1023
    int v = blockIdx.x * 128 + vl;
    const float* h = g_h[(s & 1) ^ 1];

    float acc[NB];
#pragma unroll
    for (int b = 0; b < NB; b++) acc[b] = 0.0f;

    for (int t = 0; t < 4; t++) {
        __syncthreads();
        // stage 256 u-rows: rows 0..127 -> u = t*128+r ; rows 128..255 -> 512+t*128+r
        for (int i = tid; i < 256 * NB; i += 256) {
            int ul = i & 255;
            int bb = i >> 8;
            int ug = (ul < 128) ? (t * 128 + ul) : (512 + t * 128 + (ul - 128));
            ht[ul][bb] = h[bb * NU + ug];
        }
        __syncthreads();
        int ubase = kh * 512 + t * 128;           // global u for this half
        int rbase = kh * 128;                     // ht row offset
        const float* wp = W + (size_t)ubase * NV + v;
#pragma unroll 8
        for (int ul = 0; ul < 128; ul++) {
            float w = __ldg(wp + (size_t)ul * NV);
            const float* hr = ht[rbase + ul];
#pragma unroll
            for (int q = 0; q < 8; q++) {
                float4 hq = *reinterpret_cast<const float4*>(&hr[4 * q]);
                acc[4 * q + 0] += hq.x * w;
                acc[4 * q + 1] += hq.y * w;
                acc[4 * q + 2] += hq.z * w;
                acc[4 * q + 3] += hq.w * w;
            }
        }
    }

    // combine halves: kh=1 stores partials into (reused) ht region
    __syncthreads();
    float* part = &ht[0][0];          // [vl*33 + b], 4224 floats < 9216
    if (kh == 1) {
#pragma unroll
        for (int b = 0; b < NB; b++) part[vl * 33 + b] = acc[b];
    }
    __syncthreads();
    if (kh == 0) {
        float pbv = pb[v];
        uint2 sk = g_subkey[s];
        int lane = tid & 31;
        int par = s & 1;
#pragma unroll 1
        for (int b = 0; b < NB; b++) {
            float logit = acc[b] + part[vl * 33 + b] + pbv;
            uint32_t i = (uint32_t)(b * NV + v);
            float g = gumbel_from_bits(jax_bits(sk, i));
            unsigned long long pk = pack_cand(logit + g, v);
#pragma unroll
            for (int off = 16; off > 0; off >>= 1) {
                unsigned long long o = __shfl_down_sync(0xffffffffu, pk, off);
                if (o > pk) pk = o;
            }
            if (lane == 0) atomicMax(&g_best[par][b], pk);
        }
    }
}

// ---------------- finalize step: FLOAT32 output ----------------
__global__ void fin_kernel(float* __restrict__ out, int s) {
    int b = threadIdx.x;
    if (b < NB) {
        unsigned long long p = g_best[s & 1][b];
        int v = (int)(~(unsigned int)p);
        out[b * NSTEPS + s] = (float)v;
        g_tok[b] = v;
        g_best[(s & 1) ^ 1][b] = 0ULL;
    }
}

// ---------------- launch ----------------
extern "C" void kernel_launch(void* const* d_in, const int* in_sizes, int n_in,
                              void* d_out, int out_size) {
    bool el_mode = false, byte_mode = false;
    for (int i = 0; i < n_in; i++) {
        if (in_sizes[i] == 32000)  el_mode   = true;
        if (in_sizes[i] == 128000) byte_mode = true;
    }
    const float* img  = (const float*)d_in[0];
    const float* emb  = (const float*)d_in[1];
    const float* Kw   = (const float*)d_in[2];
    const float* Rw   = (const float*)d_in[3];
    const float* bias = (const float*)d_in[4];
    const float* W    = (const float*)d_in[5];
    const float* pb   = (const float*)d_in[6];
    if (el_mode) {
        for (int i = 0; i < n_in; i++) {
            const float* p = (const float*)d_in[i];
            switch (in_sizes[i]) {
                case 3276800:  img  = p; break;
                case 8192000:  emb  = p; break;
                case 3145728:  Kw   = p; break;
                case 4194304:  Rw   = p; break;
                case 4096:     bias = p; break;
                case 32768000: W    = p; break;
                case 32000:    pb   = p; break;
                default: break;
            }
        }
    } else if (byte_mode) {
        for (int i = 0; i < n_in; i++) {
            const float* p = (const float*)d_in[i];
            switch (in_sizes[i]) {
                case 13107200:  img  = p; break;
                case 32768000:  emb  = p; break;
                case 12582912:  Kw   = p; break;
                case 16777216:  Rw   = p; break;
                case 16384:     bias = p; break;
                case 131072000: W    = p; break;
                case 128000:    pb   = p; break;
                default: break;
            }
        }
    }
    float* out = (float*)d_out;

    init_kernel<<<1, 256>>>();
    feat_kernel<<<64, 256>>>(img);
    for (int s = 0; s < NSTEPS; s++) {
        lstm_part_kernel<<<dim3(16, 8), 256>>>(emb, Kw, Rw, s);
        lstm_combine_kernel<<<128, 256>>>(bias, s);
        logits_kernel<<<250, 256>>>(W, pb, s);
        fin_kernel<<<1, 32>>>(out, s);
    }
}

// round 15
// speedup vs baseline: 9.8882x; 1.6119x over previous
#include <cuda_runtime.h>
#include <cuda_bf16.h>
#include <cstdint>
#include <math.h>

#define NB     32
#define NEMB   256
#define NFEAT  512
#define NU     1024
#define NV     32000
#define NSTEPS 128
#define KCH    224               // LSTM K per chunk (8 chunks)
#define NJ     4096              // 4 gates x 1024
#define NVT    (NV / 8)          // 4000 n-tiles of 8

// ---------------- device state ----------------
__device__ float g_feat[NB * NFEAT];
__device__ float g_h[2][NB * NU];
__device__ float g_c[NB * NU];
__device__ int   g_tok[NB];
__device__ unsigned long long g_best[2][NB];
__device__ uint2 g_subkey[NSTEPS];
__device__ float g_zpart[8 * NB * NJ];          // LSTM split-K partials
__device__ uint4 g_wpack[(size_t)NVT * 64 * 32]; // W bf16(hi,lo) B-fragments, 131MB
__device__ uint4 g_hfH[2 * 64 * 32];             // h hi A-fragments
__device__ uint4 g_hfL[2 * 64 * 32];             // h lo A-fragments

// ---------------- threefry2x32-20 core ----------------
__device__ __forceinline__ uint32_t rotl32(uint32_t x, int r) {
    return (x << r) | (x >> (32 - r));
}

__device__ __forceinline__ void tf2x32(uint32_t k0, uint32_t k1,
                                       uint32_t x0, uint32_t x1,
                                       uint32_t& o0, uint32_t& o1) {
    uint32_t ks2 = k0 ^ k1 ^ 0x1BD11BDAu;
    x0 += k0; x1 += k1;
#define TFR(r) { x0 += x1; x1 = rotl32(x1, r); x1 ^= x0; }
    TFR(13) TFR(15) TFR(26) TFR(6)   x0 += k1;  x1 += ks2 + 1u;
    TFR(17) TFR(29) TFR(16) TFR(24)  x0 += ks2; x1 += k0 + 2u;
    TFR(13) TFR(15) TFR(26) TFR(6)   x0 += k0;  x1 += k1 + 3u;
    TFR(17) TFR(29) TFR(16) TFR(24)  x0 += k1;  x1 += ks2 + 4u;
    TFR(13) TFR(15) TFR(26) TFR(6)   x0 += ks2; x1 += k0 + 5u;
#undef TFR
    o0 = x0; o1 = x1;
}

__device__ __forceinline__ uint32_t jax_bits(uint2 key, uint32_t i) {
    uint32_t o0, o1;
    tf2x32(key.x, key.y, 0u, i, o0, o1);
    return o0 ^ o1;
}

__device__ __forceinline__ float gumbel_from_bits(uint32_t bits) {
    float f = __uint_as_float((bits >> 9) | 0x3f800000u) - 1.0f;
    float u = fmaxf(f, 1.1754944e-38f);
    return -logf(-logf(u));
}

__device__ __forceinline__ unsigned long long pack_cand(float v, int idx) {
    uint32_t b = __float_as_uint(v);
    b = (b & 0x80000000u) ? ~b : (b | 0x80000000u);
    return ((unsigned long long)b << 32) | (uint32_t)(~(uint32_t)idx);
}

// ---------------- bf16 split helpers ----------------
__device__ __forceinline__ void split_bf16(float v, __nv_bfloat16& hi, __nv_bfloat16& lo) {
    hi = __float2bfloat16(v);
    lo = __float2bfloat16(v - __bfloat162float(hi));
}

__device__ __forceinline__ uint32_t pack_bf2(__nv_bfloat16 a, __nv_bfloat16 b) {
    __nv_bfloat162 h;
    h.x = a;   // low half = smaller-k element
    h.y = b;
    return *reinterpret_cast<uint32_t*>(&h);
}

// mma.sync m16n8k16 row.col bf16 -> f32 accumulate
__device__ __forceinline__ void mma16816(float* d, uint32_t a0, uint32_t a1,
                                         uint32_t a2, uint32_t a3,
                                         uint32_t b0, uint32_t b1) {
    asm volatile(
        "mma.sync.aligned.m16n8k16.row.col.f32.bf16.bf16.f32 "
        "{%0,%1,%2,%3}, {%4,%5,%6,%7}, {%8,%9}, {%0,%1,%2,%3};"
        : "+f"(d[0]), "+f"(d[1]), "+f"(d[2]), "+f"(d[3])
        : "r"(a0), "r"(a1), "r"(a2), "r"(a3), "r"(b0), "r"(b1));
}

// ---------------- init ----------------
__global__ void init_kernel() {
    int tid = threadIdx.x;
    for (int i = tid; i < NB * NU; i += 256) {
        g_h[0][i] = 0.0f;
        g_h[1][i] = 0.0f;
        g_c[i] = 0.0f;
    }
    if (tid < 64) g_best[tid >> 5][tid & 31] = 0ULL;
    if (tid == 0) {
        uint32_t k0 = 0u, k1 = 42u;   // jax.random.key(42)
        for (int s = 0; s < NSTEPS; s++) {
            uint32_t s0, s1, n0, n1;
            tf2x32(k0, k1, 0u, 1u, s0, s1);
            g_subkey[s] = make_uint2(s0, s1);
            tf2x32(k0, k1, 0u, 0u, n0, n1);
            k0 = n0; k1 = n1;
        }
    }
}

// ---------------- image feature mean ----------------
__global__ void feat_kernel(const float* __restrict__ img) {
    int idx = blockIdx.x * 256 + threadIdx.x;
    int b = idx >> 9;
    int c = idx & 511;
    float sum = 0.0f;
    const float* p = img + (size_t)b * 200 * NFEAT + c;
    for (int t = 0; t < 200; t++) sum += p[t * NFEAT];
    g_feat[idx] = sum / 200.0f;
}

// ---------------- W -> bf16(hi,lo) B-fragment pack (once per replay) -------
// fragment index fi = vt*64 + ut ; lane holds {b0_hi, b1_hi, b0_lo, b1_lo}
// B-frag layout (m16n8k16 col): n = vt*8 + (lane>>2); k = ut*16 + (lane&3)*2 (+1, +8, +9)
__global__ void wpack_kernel(const float* __restrict__ W) {
    int id = blockIdx.x * 256 + threadIdx.x;   // 0 .. 8,191,999
    int lane = id & 31;
    int fi = id >> 5;
    int ut = fi & 63;
    int vt = fi >> 6;
    int g = lane >> 2, t = lane & 3;
    int n = vt * 8 + g;
    int k0 = ut * 16 + t * 2;
    float w00 = W[(size_t)k0 * NV + n];
    float w01 = W[(size_t)(k0 + 1) * NV + n];
    float w10 = W[(size_t)(k0 + 8) * NV + n];
    float w11 = W[(size_t)(k0 + 9) * NV + n];
    __nv_bfloat16 h00, l00, h01, l01, h10, l10, h11, l11;
    split_bf16(w00, h00, l00);
    split_bf16(w01, h01, l01);
    split_bf16(w10, h10, l10);
    split_bf16(w11, h11, l11);
    g_wpack[id] = make_uint4(pack_bf2(h00, h01), pack_bf2(h10, h11),
                             pack_bf2(l00, l01), pack_bf2(l10, l11));
}

// ---------------- h -> bf16(hi,lo) A-fragments (per step) ----------------
// fi = mt*64 + ut ; a0:(m=g,k0,k0+1) a1:(m=g+8) a2:(m=g,k0+8,k0+9) a3:(m=g+8)
__global__ void hfrag_kernel(int s) {
    int id = blockIdx.x * 256 + threadIdx.x;   // 0..4095
    int lane = id & 31;
    int fi = id >> 5;
    int ut = fi & 63;
    int mt = fi >> 6;
    int g = lane >> 2, t = lane & 3;
    const float* h = g_h[(s & 1) ^ 1];
    int m0 = mt * 16 + g, m1 = m0 + 8;
    int k0 = ut * 16 + t * 2;
    float v00 = h[m0 * NU + k0],     v01 = h[m0 * NU + k0 + 1];
    float v10 = h[m1 * NU + k0],     v11 = h[m1 * NU + k0 + 1];
    float v20 = h[m0 * NU + k0 + 8], v21 = h[m0 * NU + k0 + 9];
    float v30 = h[m1 * NU + k0 + 8], v31 = h[m1 * NU + k0 + 9];
    __nv_bfloat16 h00,l00,h01,l01,h10,l10,h11,l11,h20,l20,h21,l21,h30,l30,h31,l31;
    split_bf16(v00,h00,l00); split_bf16(v01,h01,l01);
    split_bf16(v10,h10,l10); split_bf16(v11,h11,l11);
    split_bf16(v20,h20,l20); split_bf16(v21,h21,l21);
    split_bf16(v30,h30,l30); split_bf16(v31,h31,l31);
    g_hfH[id] = make_uint4(pack_bf2(h00,h01), pack_bf2(h10,h11),
                           pack_bf2(h20,h21), pack_bf2(h30,h31));
    g_hfL[id] = make_uint4(pack_bf2(l00,l01), pack_bf2(l10,l11),
                           pack_bf2(l20,l21), pack_bf2(l30,l31));
}

// ---------------- LSTM split-K partial GEMM (unchanged) ----------------
__global__ void __launch_bounds__(256, 2)
lstm_part_kernel(const float* __restrict__ emb,
                 const float* __restrict__ Kw,
                 const float* __restrict__ Rw,
                 int s) {
    __shared__ float xs[KCH][36];
    __shared__ int stok[NB];
    int tid = threadIdx.x;
    int J  = blockIdx.x * 256 + tid;
    int kc = blockIdx.y;
    int k0 = kc * KCH;

    if (tid < NB) {
        int t = (s == 0) ? 1 : g_tok[tid];
        if (t < 0 || t >= NV) t = 0;
        stok[tid] = t;
    }
    __syncthreads();
    const float* hp = g_h[s & 1];
    for (int i = tid; i < KCH * NB; i += 256) {
        int kl = i % KCH;
        int bb = i / KCH;
        int k = k0 + kl;
        float v;
        if (k < 256)      v = emb[stok[bb] * NEMB + k];
        else if (k < 768) v = g_feat[bb * NFEAT + (k - 256)];
        else              v = hp[bb * NU + (k - 768)];
        xs[kl][bb] = v;
    }
    __syncthreads();

    float acc[NB];
#pragma unroll
    for (int b = 0; b < NB; b++) acc[b] = 0.0f;

#pragma unroll 4
    for (int kl = 0; kl < KCH; kl++) {
        int k = k0 + kl;
        const float* wr = (k < 768) ? (Kw + (size_t)k * NJ)
                                    : (Rw + (size_t)(k - 768) * NJ);
        float w = __ldg(wr + J);
#pragma unroll
        for (int q = 0; q < 8; q++) {
            float4 xq = *reinterpret_cast<const float4*>(&xs[kl][4 * q]);
            acc[4 * q + 0] += xq.x * w;
            acc[4 * q + 1] += xq.y * w;
            acc[4 * q + 2] += xq.z * w;
            acc[4 * q + 3] += xq.w * w;
        }
    }

    float* zp = g_zpart + (size_t)kc * NB * NJ + J;
#pragma unroll
    for (int b = 0; b < NB; b++) zp[b * NJ] = acc[b];
}

// ---------------- LSTM combine (unchanged) ----------------
__global__ void lstm_combine_kernel(const float* __restrict__ bias, int s) {
    int idx = blockIdx.x * 256 + threadIdx.x;
    int b = idx >> 10;
    int j = idx & 1023;
    float z0 = bias[j], z1 = bias[NU + j], z2 = bias[2 * NU + j], z3 = bias[3 * NU + j];
#pragma unroll
    for (int kc = 0; kc < 8; kc++) {
        const float* zp = g_zpart + (size_t)kc * NB * NJ + b * NJ;
        z0 += zp[j];
        z1 += zp[NU + j];
        z2 += zp[2 * NU + j];
        z3 += zp[3 * NU + j];
    }
    float ig = 1.0f / (1.0f + expf(-z0));
    float fg = 1.0f / (1.0f + expf(-z1));
    float og = 1.0f / (1.0f + expf(-z3));
    float cold = g_c[b * NU + j];
    float cn = fg * cold + ig * tanhf(z2);
    float hn = og * tanhf(cn);
    g_c[b * NU + j] = cn;
    g_h[(s & 1) ^ 1][b * NU + j] = hn;
}

// ---------------- logits via bf16x2 tensor-core mma ----------------
// grid 250 x 256: 8 warps/block, warp owns 16 v (2 n-tiles), full K=1024.
__global__ void __launch_bounds__(256)
logits_mma_kernel(const float* __restrict__ pb, int s) {
    __shared__ unsigned long long sbest[NB];
    int tid = threadIdx.x;
    int warp = tid >> 5;
    int lane = tid & 31;
    int g = lane >> 2, t = lane & 3;
    if (tid < NB) sbest[tid] = 0ULL;
    __syncthreads();

    int vbase = blockIdx.x * 128 + warp * 16;
    int vt0 = vbase >> 3;                      // first of 2 n-tiles

    float d[2][2][4];
#pragma unroll
    for (int mt = 0; mt < 2; mt++)
#pragma unroll
        for (int nt = 0; nt < 2; nt++)
#pragma unroll
            for (int q = 0; q < 4; q++) d[mt][nt][q] = 0.0f;

    for (int ut = 0; ut < 64; ut++) {
        uint4 ah0 = __ldg(&g_hfH[ut * 32 + lane]);
        uint4 ah1 = __ldg(&g_hfH[(64 + ut) * 32 + lane]);
        uint4 al0 = __ldg(&g_hfL[ut * 32 + lane]);
        uint4 al1 = __ldg(&g_hfL[(64 + ut) * 32 + lane]);
#pragma unroll
        for (int nt = 0; nt < 2; nt++) {
            uint4 wb = __ldg(&g_wpack[((size_t)(vt0 + nt) * 64 + ut) * 32 + lane]);
            mma16816(d[0][nt], ah0.x, ah0.y, ah0.z, ah0.w, wb.x, wb.y);  // hi*hi
            mma16816(d[0][nt], ah0.x, ah0.y, ah0.z, ah0.w, wb.z, wb.w);  // hi*lo
            mma16816(d[0][nt], al0.x, al0.y, al0.z, al0.w, wb.x, wb.y);  // lo*hi
            mma16816(d[1][nt], ah1.x, ah1.y, ah1.z, ah1.w, wb.x, wb.y);
            mma16816(d[1][nt], ah1.x, ah1.y, ah1.z, ah1.w, wb.z, wb.w);
            mma16816(d[1][nt], al1.x, al1.y, al1.z, al1.w, wb.x, wb.y);
        }
    }

    // epilogue: +pb, gumbel, argmax
    int v0 = vbase + t * 2;
    int v2 = vbase + 8 + t * 2;
    float pb0 = pb[v0], pb1 = pb[v0 + 1], pb2 = pb[v2], pb3 = pb[v2 + 1];
    uint2 sk = g_subkey[s];
    int par = s & 1;

#pragma unroll
    for (int mt = 0; mt < 2; mt++) {
#pragma unroll
        for (int row = 0; row < 2; row++) {
            int b = mt * 16 + g + row * 8;
            uint32_t base = (uint32_t)(b * NV);
            float x0 = d[mt][0][row * 2 + 0] + pb0 + gumbel_from_bits(jax_bits(sk, base + v0));
            float x1 = d[mt][0][row * 2 + 1] + pb1 + gumbel_from_bits(jax_bits(sk, base + v0 + 1));
            float x2 = d[mt][1][row * 2 + 0] + pb2 + gumbel_from_bits(jax_bits(sk, base + v2));
            float x3 = d[mt][1][row * 2 + 1] + pb3 + gumbel_from_bits(jax_bits(sk, base + v2 + 1));
            unsigned long long pk = pack_cand(x0, v0);
            unsigned long long p1 = pack_cand(x1, v0 + 1);
            unsigned long long p2 = pack_cand(x2, v2);
            unsigned long long p3 = pack_cand(x3, v2 + 1);
            if (p1 > pk) pk = p1;
            if (p2 > pk) pk = p2;
            if (p3 > pk) pk = p3;
            unsigned long long o;
            o = __shfl_xor_sync(0xffffffffu, pk, 1); if (o > pk) pk = o;
            o = __shfl_xor_sync(0xffffffffu, pk, 2); if (o > pk) pk = o;
            if (t == 0) atomicMax(&sbest[b], pk);
        }
    }
    __syncthreads();
    if (tid < NB) atomicMax(&g_best[par][tid], sbest[tid]);
}

// ---------------- finalize step ----------------
__global__ void fin_kernel(float* __restrict__ out, int s) {
    int b = threadIdx.x;
    if (b < NB) {
        unsigned long long p = g_best[s & 1][b];
        int v = (int)(~(unsigned int)p);
        out[b * NSTEPS + s] = (float)v;
        g_tok[b] = v;
        g_best[(s & 1) ^ 1][b] = 0ULL;
    }
}

// ---------------- launch ----------------
extern "C" void kernel_launch(void* const* d_in, const int* in_sizes, int n_in,
                              void* d_out, int out_size) {
    bool el_mode = false, byte_mode = false;
    for (int i = 0; i < n_in; i++) {
        if (in_sizes[i] == 32000)  el_mode   = true;
        if (in_sizes[i] == 128000) byte_mode = true;
    }
    const float* img  = (const float*)d_in[0];
    const float* emb  = (const float*)d_in[1];
    const float* Kw   = (const float*)d_in[2];
    const float* Rw   = (const float*)d_in[3];
    const float* bias = (const float*)d_in[4];
    const float* W    = (const float*)d_in[5];
    const float* pb   = (const float*)d_in[6];
    if (el_mode) {
        for (int i = 0; i < n_in; i++) {
            const float* p = (const float*)d_in[i];
            switch (in_sizes[i]) {
                case 3276800:  img  = p; break;
                case 8192000:  emb  = p; break;
                case 3145728:  Kw   = p; break;
                case 4194304:  Rw   = p; break;
                case 4096:     bias = p; break;
                case 32768000: W    = p; break;
                case 32000:    pb   = p; break;
                default: break;
            }
        }
    } else if (byte_mode) {
        for (int i = 0; i < n_in; i++) {
            const float* p = (const float*)d_in[i];
            switch (in_sizes[i]) {
                case 13107200:  img  = p; break;
                case 32768000:  emb  = p; break;
                case 12582912:  Kw   = p; break;
                case 16777216:  Rw   = p; break;
                case 16384:     bias = p; break;
                case 131072000: W    = p; break;
                case 128000:    pb   = p; break;
                default: break;
            }
        }
    }
    float* out = (float*)d_out;

    init_kernel<<<1, 256>>>();
    feat_kernel<<<64, 256>>>(img);
    wpack_kernel<<<32000, 256>>>(W);
    for (int s = 0; s < NSTEPS; s++) {
        lstm_part_kernel<<<dim3(16, 8), 256>>>(emb, Kw, Rw, s);
        lstm_combine_kernel<<<128, 256>>>(bias, s);
        hfrag_kernel<<<16, 256>>>(s);
        logits_mma_kernel<<<250, 256>>>(pb, s);
        fin_kernel<<<1, 32>>>(out, s);
    }
}

// round 16
// speedup vs baseline: 14.9297x; 1.5098x over previous
#include <cuda_runtime.h>
#include <cuda_bf16.h>
#include <cstdint>
#include <math.h>

#define NB     32
#define NEMB   256
#define NFEAT  512
#define NU     1024
#define NV     32000
#define NSTEPS 128
#define NJ     4096              // 4 gates x 1024
#define NVT    (NV / 8)          // 4000 logits n-tiles
#define NTL    (NJ / 8)          // 512 lstm n-tiles
#define UTL    112               // lstm k-tiles (1792/16)
#define KCQ    28                // lstm k-tiles per chunk (4 chunks)

// ---------------- device state ----------------
__device__ float g_feat[NB * NFEAT];
__device__ float g_c[NB * NU];
__device__ unsigned long long g_best[2][NB];
__device__ uint2 g_subkey[NSTEPS];
__device__ float g_zpart[4 * NB * NJ];            // lstm split-K partials (2MB)
__device__ uint4 g_wpack[(size_t)NVT * 64 * 32];  // logits W frags, 131MB
__device__ uint4 g_lw[(size_t)NTL * UTL * 32];    // lstm W frags, 29MB
__device__ uint4 g_embfH[16 * 2 * 32],  g_embfL[16 * 2 * 32];   // x emb frags
__device__ uint4 g_featfH[32 * 2 * 32], g_featfL[32 * 2 * 32];  // x feat frags
__device__ uint4 g_hfH[2][64 * 2 * 32], g_hfL[2][64 * 2 * 32];  // h frags (parity)

// ---------------- threefry2x32-20 core ----------------
__device__ __forceinline__ uint32_t rotl32(uint32_t x, int r) {
    return (x << r) | (x >> (32 - r));
}

__device__ __forceinline__ void tf2x32(uint32_t k0, uint32_t k1,
                                       uint32_t x0, uint32_t x1,
                                       uint32_t& o0, uint32_t& o1) {
    uint32_t ks2 = k0 ^ k1 ^ 0x1BD11BDAu;
    x0 += k0; x1 += k1;
#define TFR(r) { x0 += x1; x1 = rotl32(x1, r); x1 ^= x0; }
    TFR(13) TFR(15) TFR(26) TFR(6)   x0 += k1;  x1 += ks2 + 1u;
    TFR(17) TFR(29) TFR(16) TFR(24)  x0 += ks2; x1 += k0 + 2u;
    TFR(13) TFR(15) TFR(26) TFR(6)   x0 += k0;  x1 += k1 + 3u;
    TFR(17) TFR(29) TFR(16) TFR(24)  x0 += k1;  x1 += ks2 + 4u;
    TFR(13) TFR(15) TFR(26) TFR(6)   x0 += ks2; x1 += k0 + 5u;
#undef TFR
    o0 = x0; o1 = x1;
}

__device__ __forceinline__ uint32_t jax_bits(uint2 key, uint32_t i) {
    uint32_t o0, o1;
    tf2x32(key.x, key.y, 0u, i, o0, o1);
    return o0 ^ o1;
}

__device__ __forceinline__ float gumbel_from_bits(uint32_t bits) {
    float f = __uint_as_float((bits >> 9) | 0x3f800000u) - 1.0f;
    float u = fmaxf(f, 1.1754944e-38f);
    return -logf(-logf(u));
}

__device__ __forceinline__ unsigned long long pack_cand(float v, int idx) {
    uint32_t b = __float_as_uint(v);
    b = (b & 0x80000000u) ? ~b : (b | 0x80000000u);
    return ((unsigned long long)b << 32) | (uint32_t)(~(uint32_t)idx);
}

// ---------------- bf16 split helpers ----------------
__device__ __forceinline__ void split_bf16(float v, __nv_bfloat16& hi, __nv_bfloat16& lo) {
    hi = __float2bfloat16(v);
    lo = __float2bfloat16(v - __bfloat162float(hi));
}

__device__ __forceinline__ uint32_t pack_bf2(__nv_bfloat16 a, __nv_bfloat16 b) {
    __nv_bfloat162 h;
    h.x = a;
    h.y = b;
    return *reinterpret_cast<uint32_t*>(&h);
}

__device__ __forceinline__ void mma16816(float* d, uint32_t a0, uint32_t a1,
                                         uint32_t a2, uint32_t a3,
                                         uint32_t b0, uint32_t b1) {
    asm volatile(
        "mma.sync.aligned.m16n8k16.row.col.f32.bf16.bf16.f32 "
        "{%0,%1,%2,%3}, {%4,%5,%6,%7}, {%8,%9}, {%0,%1,%2,%3};"
        : "+f"(d[0]), "+f"(d[1]), "+f"(d[2]), "+f"(d[3])
        : "r"(a0), "r"(a1), "r"(a2), "r"(a3), "r"(b0), "r"(b1));
}

// ---------------- init ----------------
__global__ void init_kernel() {
    int id = blockIdx.x * 256 + threadIdx.x;
    int n = gridDim.x * 256;
    for (int i = id; i < NB * NU; i += n) g_c[i] = 0.0f;
    uint4 z4 = make_uint4(0, 0, 0, 0);
    for (int i = id; i < 64 * 2 * 32; i += n) { g_hfH[0][i] = z4; g_hfL[0][i] = z4; }
    if (id < 64) g_best[id >> 5][id & 31] = 0ULL;
    if (id == 0) {
        uint32_t k0 = 0u, k1 = 42u;   // jax.random.key(42)
        for (int s = 0; s < NSTEPS; s++) {
            uint32_t s0, s1, n0, n1;
            tf2x32(k0, k1, 0u, 1u, s0, s1);
            g_subkey[s] = make_uint2(s0, s1);
            tf2x32(k0, k1, 0u, 0u, n0, n1);
            k0 = n0; k1 = n1;
        }
    }
}

// ---------------- image feature mean ----------------
__global__ void feat_kernel(const float* __restrict__ img) {
    int idx = blockIdx.x * 256 + threadIdx.x;
    int b = idx >> 9;
    int c = idx & 511;
    float sum = 0.0f;
    const float* p = img + (size_t)b * 200 * NFEAT + c;
    for (int t = 0; t < 200; t++) sum += p[t * NFEAT];
    g_feat[idx] = sum / 200.0f;
}

// ---------------- feat -> A-fragments (once per replay) ----------------
__global__ void featpack_kernel() {
    int id = blockIdx.x * 256 + threadIdx.x;   // 0..2047
    int lane = id & 31;
    int fi = id >> 5;
    int mt = fi & 1;
    int uf = fi >> 1;                          // 0..31
    int g = lane >> 2, t = lane & 3;
    int m0 = mt * 16 + g, m1 = m0 + 8;
    int f0 = uf * 16 + t * 2;
    float v00 = g_feat[m0 * NFEAT + f0],     v01 = g_feat[m0 * NFEAT + f0 + 1];
    float v10 = g_feat[m1 * NFEAT + f0],     v11 = g_feat[m1 * NFEAT + f0 + 1];
    float v20 = g_feat[m0 * NFEAT + f0 + 8], v21 = g_feat[m0 * NFEAT + f0 + 9];
    float v30 = g_feat[m1 * NFEAT + f0 + 8], v31 = g_feat[m1 * NFEAT + f0 + 9];
    __nv_bfloat16 h00,l00,h01,l01,h10,l10,h11,l11,h20,l20,h21,l21,h30,l30,h31,l31;
    split_bf16(v00,h00,l00); split_bf16(v01,h01,l01);
    split_bf16(v10,h10,l10); split_bf16(v11,h11,l11);
    split_bf16(v20,h20,l20); split_bf16(v21,h21,l21);
    split_bf16(v30,h30,l30); split_bf16(v31,h31,l31);
    int o = (uf * 2 + mt) * 32 + lane;
    g_featfH[o] = make_uint4(pack_bf2(h00,h01), pack_bf2(h10,h11),
                             pack_bf2(h20,h21), pack_bf2(h30,h31));
    g_featfL[o] = make_uint4(pack_bf2(l00,l01), pack_bf2(l10,l11),
                             pack_bf2(l20,l21), pack_bf2(l30,l31));
}

// ---------------- logits W -> B-fragments (once per replay) ----------------
__global__ void wpack_kernel(const float* __restrict__ W) {
    int id = blockIdx.x * 256 + threadIdx.x;
    int lane = id & 31;
    int fi = id >> 5;
    int ut = fi & 63;
    int vt = fi >> 6;
    int g = lane >> 2, t = lane & 3;
    int n = vt * 8 + g;
    int k0 = ut * 16 + t * 2;
    float w00 = W[(size_t)k0 * NV + n];
    float w01 = W[(size_t)(k0 + 1) * NV + n];
    float w10 = W[(size_t)(k0 + 8) * NV + n];
    float w11 = W[(size_t)(k0 + 9) * NV + n];
    __nv_bfloat16 h00, l00, h01, l01, h10, l10, h11, l11;
    split_bf16(w00, h00, l00);
    split_bf16(w01, h01, l01);
    split_bf16(w10, h10, l10);
    split_bf16(w11, h11, l11);
    g_wpack[id] = make_uint4(pack_bf2(h00, h01), pack_bf2(h10, h11),
                             pack_bf2(l00, l01), pack_bf2(l10, l11));
}

// ---------------- LSTM W -> B-fragments (once per replay) ----------------
__global__ void lwpack_kernel(const float* __restrict__ Kw,
                              const float* __restrict__ Rw) {
    int id = blockIdx.x * 256 + threadIdx.x;   // 0 .. 1,835,007
    int lane = id & 31;
    int fi = id >> 5;
    int ut = fi % UTL;
    int nt = fi / UTL;
    int g = lane >> 2, t = lane & 3;
    int n = nt * 8 + g;
    int k0 = ut * 16 + t * 2;
    const float* base = (k0 < 768) ? (Kw + (size_t)k0 * NJ)
                                   : (Rw + (size_t)(k0 - 768) * NJ);
    float w00 = base[n];
    float w01 = base[NJ + n];
    float w10 = base[8 * NJ + n];
    float w11 = base[9 * NJ + n];
    __nv_bfloat16 h00, l00, h01, l01, h10, l10, h11, l11;
    split_bf16(w00, h00, l00);
    split_bf16(w01, h01, l01);
    split_bf16(w10, h10, l10);
    split_bf16(w11, h11, l11);
    g_lw[id] = make_uint4(pack_bf2(h00, h01), pack_bf2(h10, h11),
                          pack_bf2(l00, l01), pack_bf2(l10, l11));
}

// ---------------- LSTM GEMM via tensor cores (split-K partials) ----------
// grid (64, 4): x = nt-group (8 warps = 8 nt), y = k-chunk (28 ut).
__global__ void __launch_bounds__(256)
lstm_mma_kernel(int s) {
    int tid = threadIdx.x;
    int warp = tid >> 5;
    int lane = tid & 31;
    int nt = blockIdx.x * 8 + warp;     // 0..511
    int kc = blockIdx.y;                // 0..3
    int par = s & 1;                    // h_prev frag parity

    float d[2][4];
#pragma unroll
    for (int mt = 0; mt < 2; mt++)
#pragma unroll
        for (int q = 0; q < 4; q++) d[mt][q] = 0.0f;

    const uint4* lw = g_lw + ((size_t)nt * UTL + kc * KCQ) * 32 + lane;
#pragma unroll 2
    for (int u = 0; u < KCQ; u++) {
        int ut = kc * KCQ + u;
        const uint4 *bH, *bL;
        if (ut < 16)      { bH = g_embfH  + (ut * 2) * 32;        bL = g_embfL  + (ut * 2) * 32; }
        else if (ut < 48) { bH = g_featfH + ((ut - 16) * 2) * 32; bL = g_featfL + ((ut - 16) * 2) * 32; }
        else              { bH = g_hfH[par] + ((ut - 48) * 2) * 32; bL = g_hfL[par] + ((ut - 48) * 2) * 32; }
        uint4 ah0 = bH[lane];
        uint4 ah1 = bH[32 + lane];
        uint4 al0 = bL[lane];
        uint4 al1 = bL[32 + lane];
        uint4 wb = lw[(size_t)u * 32];
        mma16816(d[0], ah0.x, ah0.y, ah0.z, ah0.w, wb.x, wb.y);  // hi*hi
        mma16816(d[0], ah0.x, ah0.y, ah0.z, ah0.w, wb.z, wb.w);  // hi*lo
        mma16816(d[0], al0.x, al0.y, al0.z, al0.w, wb.x, wb.y);  // lo*hi
        mma16816(d[1], ah1.x, ah1.y, ah1.z, ah1.w, wb.x, wb.y);
        mma16816(d[1], ah1.x, ah1.y, ah1.z, ah1.w, wb.z, wb.w);
        mma16816(d[1], al1.x, al1.y, al1.z, al1.w, wb.x, wb.y);
    }

    int g = lane >> 2, t = lane & 3;
#pragma unroll
    for (int mt = 0; mt < 2; mt++) {
#pragma unroll
        for (int row = 0; row < 2; row++) {
            int b = mt * 16 + g + row * 8;
            float* zp = g_zpart + (size_t)kc * NB * NJ + b * NJ + nt * 8 + t * 2;
            zp[0] = d[mt][row * 2 + 0];
            zp[1] = d[mt][row * 2 + 1];
        }
    }
}

// ---------------- LSTM combine: partials -> gates -> h-fragments ----------
__global__ void lstm_combine_kernel(const float* __restrict__ bias, int s) {
    int idx = blockIdx.x * 256 + threadIdx.x;   // 0..32767
    int b = idx >> 10;
    int j = idx & 1023;
    float z0 = bias[j], z1 = bias[NU + j], z2 = bias[2 * NU + j], z3 = bias[3 * NU + j];
#pragma unroll
    for (int kc = 0; kc < 4; kc++) {
        const float* zp = g_zpart + (size_t)kc * NB * NJ + b * NJ;
        z0 += zp[j];
        z1 += zp[NU + j];
        z2 += zp[2 * NU + j];
        z3 += zp[3 * NU + j];
    }
    float ig = 1.0f / (1.0f + expf(-z0));
    float fg = 1.0f / (1.0f + expf(-z1));
    float og = 1.0f / (1.0f + expf(-z3));
    float cold = g_c[b * NU + j];
    float cn = fg * cold + ig * tanhf(z2);
    float hn = og * tanhf(cn);
    g_c[b * NU + j] = cn;

    // write h directly as bf16(hi,lo) A-fragment elements
    int p = (s & 1) ^ 1;
    int mt = b >> 4, ml = b & 15;
    int g = ml & 7, rr = ml >> 3;
    int ut = j >> 4, kl = j & 15;
    int t = (kl & 7) >> 1, half = kl & 1, rhi = (kl >= 8);
    int lane = g * 4 + t;
    int reg = rr + rhi * 2;
    __nv_bfloat16 hi, lo;
    split_bf16(hn, hi, lo);
    int o = (ut * 2 + mt) * 32 + lane;
    reinterpret_cast<unsigned short*>(&g_hfH[p][o])[reg * 2 + half] =
        *reinterpret_cast<unsigned short*>(&hi);
    reinterpret_cast<unsigned short*>(&g_hfL[p][o])[reg * 2 + half] =
        *reinterpret_cast<unsigned short*>(&lo);
}

// ---------------- logits via tensor-core mma ----------------
__global__ void __launch_bounds__(256)
logits_mma_kernel(const float* __restrict__ pb, int s) {
    __shared__ unsigned long long sbest[NB];
    int tid = threadIdx.x;
    int warp = tid >> 5;
    int lane = tid & 31;
    int g = lane >> 2, t = lane & 3;
    int p = (s & 1) ^ 1;
    if (tid < NB) sbest[tid] = 0ULL;
    __syncthreads();

    int vbase = blockIdx.x * 128 + warp * 16;
    int vt0 = vbase >> 3;

    float d[2][2][4];
#pragma unroll
    for (int mt = 0; mt < 2; mt++)
#pragma unroll
        for (int nt = 0; nt < 2; nt++)
#pragma unroll
            for (int q = 0; q < 4; q++) d[mt][nt][q] = 0.0f;

    const uint4* HH = g_hfH[p];
    const uint4* LL = g_hfL[p];
    for (int ut = 0; ut < 64; ut++) {
        uint4 ah0 = __ldg(&HH[(ut * 2 + 0) * 32 + lane]);
        uint4 ah1 = __ldg(&HH[(ut * 2 + 1) * 32 + lane]);
        uint4 al0 = __ldg(&LL[(ut * 2 + 0) * 32 + lane]);
        uint4 al1 = __ldg(&LL[(ut * 2 + 1) * 32 + lane]);
#pragma unroll
        for (int nt = 0; nt < 2; nt++) {
            uint4 wb = __ldg(&g_wpack[((size_t)(vt0 + nt) * 64 + ut) * 32 + lane]);
            mma16816(d[0][nt], ah0.x, ah0.y, ah0.z, ah0.w, wb.x, wb.y);
            mma16816(d[0][nt], ah0.x, ah0.y, ah0.z, ah0.w, wb.z, wb.w);
            mma16816(d[0][nt], al0.x, al0.y, al0.z, al0.w, wb.x, wb.y);
            mma16816(d[1][nt], ah1.x, ah1.y, ah1.z, ah1.w, wb.x, wb.y);
            mma16816(d[1][nt], ah1.x, ah1.y, ah1.z, ah1.w, wb.z, wb.w);
            mma16816(d[1][nt], al1.x, al1.y, al1.z, al1.w, wb.x, wb.y);
        }
    }

    int v0 = vbase + t * 2;
    int v2 = vbase + 8 + t * 2;
    float pb0 = pb[v0], pb1 = pb[v0 + 1], pb2 = pb[v2], pb3 = pb[v2 + 1];
    uint2 sk = g_subkey[s];
    int par = s & 1;

#pragma unroll
    for (int mt = 0; mt < 2; mt++) {
#pragma unroll
        for (int row = 0; row < 2; row++) {
            int b = mt * 16 + g + row * 8;
            uint32_t base = (uint32_t)(b * NV);
            float x0 = d[mt][0][row * 2 + 0] + pb0 + gumbel_from_bits(jax_bits(sk, base + v0));
            float x1 = d[mt][0][row * 2 + 1] + pb1 + gumbel_from_bits(jax_bits(sk, base + v0 + 1));
            float x2 = d[mt][1][row * 2 + 0] + pb2 + gumbel_from_bits(jax_bits(sk, base + v2));
            float x3 = d[mt][1][row * 2 + 1] + pb3 + gumbel_from_bits(jax_bits(sk, base + v2 + 1));
            unsigned long long pk = pack_cand(x0, v0);
            unsigned long long p1 = pack_cand(x1, v0 + 1);
            unsigned long long p2 = pack_cand(x2, v2);
            unsigned long long p3 = pack_cand(x3, v2 + 1);
            if (p1 > pk) pk = p1;
            if (p2 > pk) pk = p2;
            if (p3 > pk) pk = p3;
            unsigned long long o;
            o = __shfl_xor_sync(0xffffffffu, pk, 1); if (o > pk) pk = o;
            o = __shfl_xor_sync(0xffffffffu, pk, 2); if (o > pk) pk = o;
            if (t == 0) atomicMax(&sbest[b], pk);
        }
    }
    __syncthreads();
    if (tid < NB) atomicMax(&g_best[par][tid], sbest[tid]);
}

// ---------------- finalize + emb-fragment pack (one 1024-thread block) -----
__global__ void finpack_kernel(const float* __restrict__ emb,
                               float* __restrict__ out, int s) {
    __shared__ int stok[NB];
    int tid = threadIdx.x;
    if (tid < NB) {
        if (s >= 0) {
            unsigned long long pk = g_best[s & 1][tid];
            int v = (int)(~(unsigned int)pk);
            out[tid * NSTEPS + s] = (float)v;
            g_best[(s & 1) ^ 1][tid] = 0ULL;
            stok[tid] = v;
        } else {
            stok[tid] = 1;   // START_TOKEN
        }
    }
    __syncthreads();

    // pack emb rows for next step's LSTM x-fragments (ut 0..15)
    int lane = tid & 31;
    int fi = tid >> 5;           // 0..31
    int mt = fi & 1;
    int ut = fi >> 1;            // 0..15
    int g = lane >> 2, t = lane & 3;
    int m0 = mt * 16 + g, m1 = m0 + 8;
    int k0 = ut * 16 + t * 2;
    const float* e0 = emb + (size_t)stok[m0] * NEMB;
    const float* e1 = emb + (size_t)stok[m1] * NEMB;
    float v00 = e0[k0],     v01 = e0[k0 + 1];
    float v10 = e1[k0],     v11 = e1[k0 + 1];
    float v20 = e0[k0 + 8], v21 = e0[k0 + 9];
    float v30 = e1[k0 + 8], v31 = e1[k0 + 9];
    __nv_bfloat16 h00,l00,h01,l01,h10,l10,h11,l11,h20,l20,h21,l21,h30,l30,h31,l31;
    split_bf16(v00,h00,l00); split_bf16(v01,h01,l01);
    split_bf16(v10,h10,l10); split_bf16(v11,h11,l11);
    split_bf16(v20,h20,l20); split_bf16(v21,h21,l21);
    split_bf16(v30,h30,l30); split_bf16(v31,h31,l31);
    int o = (ut * 2 + mt) * 32 + lane;
    g_embfH[o] = make_uint4(pack_bf2(h00,h01), pack_bf2(h10,h11),
                            pack_bf2(h20,h21), pack_bf2(h30,h31));
    g_embfL[o] = make_uint4(pack_bf2(l00,l01), pack_bf2(l10,l11),
                            pack_bf2(l20,l21), pack_bf2(l30,l31));
}

// ---------------- launch ----------------
extern "C" void kernel_launch(void* const* d_in, const int* in_sizes, int n_in,
                              void* d_out, int out_size) {
    bool el_mode = false, byte_mode = false;
    for (int i = 0; i < n_in; i++) {
        if (in_sizes[i] == 32000)  el_mode   = true;
        if (in_sizes[i] == 128000) byte_mode = true;
    }
    const float* img  = (const float*)d_in[0];
    const float* emb  = (const float*)d_in[1];
    const float* Kw   = (const float*)d_in[2];
    const float* Rw   = (const float*)d_in[3];
    const float* bias = (const float*)d_in[4];
    const float* W    = (const float*)d_in[5];
    const float* pb   = (const float*)d_in[6];
    if (el_mode) {
        for (int i = 0; i < n_in; i++) {
            const float* p = (const float*)d_in[i];
            switch (in_sizes[i]) {
                case 3276800:  img  = p; break;
                case 8192000:  emb  = p; break;
                case 3145728:  Kw   = p; break;
                case 4194304:  Rw   = p; break;
                case 4096:     bias = p; break;
                case 32768000: W    = p; break;
                case 32000:    pb   = p; break;
                default: break;
            }
        }
    } else if (byte_mode) {
        for (int i = 0; i < n_in; i++) {
            const float* p = (const float*)d_in[i];
            switch (in_sizes[i]) {
                case 13107200:  img  = p; break;
                case 32768000:  emb  = p; break;
                case 12582912:  Kw   = p; break;
                case 16777216:  Rw   = p; break;
                case 16384:     bias = p; break;
                case 131072000: W    = p; break;
                case 128000:    pb   = p; break;
                default: break;
            }
        }
    }
    float* out = (float*)d_out;

    init_kernel<<<64, 256>>>();
    feat_kernel<<<64, 256>>>(img);
    featpack_kernel<<<8, 256>>>();
    wpack_kernel<<<32000, 256>>>(W);
    lwpack_kernel<<<7168, 256>>>(Kw, Rw);
    finpack_kernel<<<1, 1024>>>(emb, out, -1);
    for (int s = 0; s < NSTEPS; s++) {
        lstm_mma_kernel<<<dim3(64, 4), 256>>>(s);
        lstm_combine_kernel<<<128, 256>>>(bias, s);
        logits_mma_kernel<<<250, 256>>>(pb, s);
        finpack_kernel<<<1, 1024>>>(emb, out, s);
    }
}

// round 17
// speedup vs baseline: 14.9971x; 1.0045x over previous
#include <cuda_runtime.h>
#include <cuda_bf16.h>
#include <cstdint>
#include <math.h>

#define NB     32
#define NEMB   256
#define NFEAT  512
#define NU     1024
#define NV     32000
#define NSTEPS 128
#define NJ     4096              // 4 gates x 1024
#define NVT    (NV / 8)          // 4000 logits n-tiles
#define NTL    (NJ / 8)          // 512 lstm n-tiles
#define UTL    112               // lstm k-tiles (1792/16)
#define KCQ    56                // lstm k-tiles per chunk (2 chunks)

// ---------------- device state ----------------
__device__ float g_feat[NB * NFEAT];
__device__ float g_c[NB * NU];
__device__ unsigned long long g_best[2][NB];
__device__ uint2 g_subkey[NSTEPS];
__device__ float g_zpart[2 * NB * NJ];            // lstm split-K partials (1MB)
__device__ uint4 g_wpack[(size_t)NVT * 64 * 32];  // logits W frags, 131MB
__device__ uint4 g_lw[(size_t)NTL * UTL * 32];    // lstm W frags, 29MB
__device__ uint4 g_embfH[16 * 2 * 32],  g_embfL[16 * 2 * 32];   // x emb frags
__device__ uint4 g_featfH[32 * 2 * 32], g_featfL[32 * 2 * 32];  // x feat frags
__device__ uint4 g_hfH[2][64 * 2 * 32], g_hfL[2][64 * 2 * 32];  // h frags (parity)

// ---------------- threefry2x32-20 core ----------------
__device__ __forceinline__ uint32_t rotl32(uint32_t x, int r) {
    return (x << r) | (x >> (32 - r));
}

__device__ __forceinline__ void tf2x32(uint32_t k0, uint32_t k1,
                                       uint32_t x0, uint32_t x1,
                                       uint32_t& o0, uint32_t& o1) {
    uint32_t ks2 = k0 ^ k1 ^ 0x1BD11BDAu;
    x0 += k0; x1 += k1;
#define TFR(r) { x0 += x1; x1 = rotl32(x1, r); x1 ^= x0; }
    TFR(13) TFR(15) TFR(26) TFR(6)   x0 += k1;  x1 += ks2 + 1u;
    TFR(17) TFR(29) TFR(16) TFR(24)  x0 += ks2; x1 += k0 + 2u;
    TFR(13) TFR(15) TFR(26) TFR(6)   x0 += k0;  x1 += k1 + 3u;
    TFR(17) TFR(29) TFR(16) TFR(24)  x0 += k1;  x1 += ks2 + 4u;
    TFR(13) TFR(15) TFR(26) TFR(6)   x0 += ks2; x1 += k0 + 5u;
#undef TFR
    o0 = x0; o1 = x1;
}

__device__ __forceinline__ uint32_t jax_bits(uint2 key, uint32_t i) {
    uint32_t o0, o1;
    tf2x32(key.x, key.y, 0u, i, o0, o1);
    return o0 ^ o1;
}

__device__ __forceinline__ float gumbel_from_bits(uint32_t bits) {
    float f = __uint_as_float((bits >> 9) | 0x3f800000u) - 1.0f;
    float u = fmaxf(f, 1.1754944e-38f);
    return -logf(-logf(u));
}

__device__ __forceinline__ unsigned long long pack_cand(float v, int idx) {
    uint32_t b = __float_as_uint(v);
    b = (b & 0x80000000u) ? ~b : (b | 0x80000000u);
    return ((unsigned long long)b << 32) | (uint32_t)(~(uint32_t)idx);
}

// ---------------- bf16 split helpers ----------------
__device__ __forceinline__ void split_bf16(float v, __nv_bfloat16& hi, __nv_bfloat16& lo) {
    hi = __float2bfloat16(v);
    lo = __float2bfloat16(v - __bfloat162float(hi));
}

__device__ __forceinline__ uint32_t pack_bf2(__nv_bfloat16 a, __nv_bfloat16 b) {
    __nv_bfloat162 h;
    h.x = a;
    h.y = b;
    return *reinterpret_cast<uint32_t*>(&h);
}

__device__ __forceinline__ void mma16816(float* d, uint32_t a0, uint32_t a1,
                                         uint32_t a2, uint32_t a3,
                                         uint32_t b0, uint32_t b1) {
    asm volatile(
        "mma.sync.aligned.m16n8k16.row.col.f32.bf16.bf16.f32 "
        "{%0,%1,%2,%3}, {%4,%5,%6,%7}, {%8,%9}, {%0,%1,%2,%3};"
        : "+f"(d[0]), "+f"(d[1]), "+f"(d[2]), "+f"(d[3])
        : "r"(a0), "r"(a1), "r"(a2), "r"(a3), "r"(b0), "r"(b1));
}

// ---------------- init ----------------
__global__ void init_kernel() {
    int id = blockIdx.x * 256 + threadIdx.x;
    int n = gridDim.x * 256;
    for (int i = id; i < NB * NU; i += n) g_c[i] = 0.0f;
    uint4 z4 = make_uint4(0, 0, 0, 0);
    for (int i = id; i < 64 * 2 * 32; i += n) { g_hfH[0][i] = z4; g_hfL[0][i] = z4; }
    if (id < 64) g_best[id >> 5][id & 31] = 0ULL;
    if (id == 0) {
        uint32_t k0 = 0u, k1 = 42u;   // jax.random.key(42)
        for (int s = 0; s < NSTEPS; s++) {
            uint32_t s0, s1, n0, n1;
            tf2x32(k0, k1, 0u, 1u, s0, s1);
            g_subkey[s] = make_uint2(s0, s1);
            tf2x32(k0, k1, 0u, 0u, n0, n1);
            k0 = n0; k1 = n1;
        }
    }
}

// ---------------- image feature mean ----------------
__global__ void feat_kernel(const float* __restrict__ img) {
    int idx = blockIdx.x * 256 + threadIdx.x;
    int b = idx >> 9;
    int c = idx & 511;
    float sum = 0.0f;
    const float* p = img + (size_t)b * 200 * NFEAT + c;
    for (int t = 0; t < 200; t++) sum += p[t * NFEAT];
    g_feat[idx] = sum / 200.0f;
}

// ---------------- feat -> A-fragments (once per replay) ----------------
__global__ void featpack_kernel() {
    int id = blockIdx.x * 256 + threadIdx.x;   // 0..2047
    int lane = id & 31;
    int fi = id >> 5;
    int mt = fi & 1;
    int uf = fi >> 1;                          // 0..31
    int g = lane >> 2, t = lane & 3;
    int m0 = mt * 16 + g, m1 = m0 + 8;
    int f0 = uf * 16 + t * 2;
    float v00 = g_feat[m0 * NFEAT + f0],     v01 = g_feat[m0 * NFEAT + f0 + 1];
    float v10 = g_feat[m1 * NFEAT + f0],     v11 = g_feat[m1 * NFEAT + f0 + 1];
    float v20 = g_feat[m0 * NFEAT + f0 + 8], v21 = g_feat[m0 * NFEAT + f0 + 9];
    float v30 = g_feat[m1 * NFEAT + f0 + 8], v31 = g_feat[m1 * NFEAT + f0 + 9];
    __nv_bfloat16 h00,l00,h01,l01,h10,l10,h11,l11,h20,l20,h21,l21,h30,l30,h31,l31;
    split_bf16(v00,h00,l00); split_bf16(v01,h01,l01);
    split_bf16(v10,h10,l10); split_bf16(v11,h11,l11);
    split_bf16(v20,h20,l20); split_bf16(v21,h21,l21);
    split_bf16(v30,h30,l30); split_bf16(v31,h31,l31);
    int o = (uf * 2 + mt) * 32 + lane;
    g_featfH[o] = make_uint4(pack_bf2(h00,h01), pack_bf2(h10,h11),
                             pack_bf2(h20,h21), pack_bf2(h30,h31));
    g_featfL[o] = make_uint4(pack_bf2(l00,l01), pack_bf2(l10,l11),
                             pack_bf2(l20,l21), pack_bf2(l30,l31));
}

// ---------------- logits W -> B-fragments (once per replay) ----------------
__global__ void wpack_kernel(const float* __restrict__ W) {
    int id = blockIdx.x * 256 + threadIdx.x;
    int lane = id & 31;
    int fi = id >> 5;
    int ut = fi & 63;
    int vt = fi >> 6;
    int g = lane >> 2, t = lane & 3;
    int n = vt * 8 + g;
    int k0 = ut * 16 + t * 2;
    float w00 = W[(size_t)k0 * NV + n];
    float w01 = W[(size_t)(k0 + 1) * NV + n];
    float w10 = W[(size_t)(k0 + 8) * NV + n];
    float w11 = W[(size_t)(k0 + 9) * NV + n];
    __nv_bfloat16 h00, l00, h01, l01, h10, l10, h11, l11;
    split_bf16(w00, h00, l00);
    split_bf16(w01, h01, l01);
    split_bf16(w10, h10, l10);
    split_bf16(w11, h11, l11);
    g_wpack[id] = make_uint4(pack_bf2(h00, h01), pack_bf2(h10, h11),
                             pack_bf2(l00, l01), pack_bf2(l10, l11));
}

// ---------------- LSTM W -> B-fragments (once per replay) ----------------
__global__ void lwpack_kernel(const float* __restrict__ Kw,
                              const float* __restrict__ Rw) {
    int id = blockIdx.x * 256 + threadIdx.x;   // 0 .. 1,835,007
    int lane = id & 31;
    int fi = id >> 5;
    int ut = fi % UTL;
    int nt = fi / UTL;
    int g = lane >> 2, t = lane & 3;
    int n = nt * 8 + g;
    int k0 = ut * 16 + t * 2;
    const float* base = (k0 < 768) ? (Kw + (size_t)k0 * NJ)
                                   : (Rw + (size_t)(k0 - 768) * NJ);
    float w00 = base[n];
    float w01 = base[NJ + n];
    float w10 = base[8 * NJ + n];
    float w11 = base[9 * NJ + n];
    __nv_bfloat16 h00, l00, h01, l01, h10, l10, h11, l11;
    split_bf16(w00, h00, l00);
    split_bf16(w01, h01, l01);
    split_bf16(w10, h10, l10);
    split_bf16(w11, h11, l11);
    g_lw[id] = make_uint4(pack_bf2(h00, h01), pack_bf2(h10, h11),
                          pack_bf2(l00, l01), pack_bf2(l10, l11));
}

// ---------------- LSTM GEMM via tensor cores (split-K 2 chunks) ----------
// grid (64, 2): x = nt-group (8 warps = 8 nt), y = k-chunk (56 ut).
__global__ void __launch_bounds__(256, 2)
lstm_mma_kernel(int s) {
    int tid = threadIdx.x;
    int warp = tid >> 5;
    int lane = tid & 31;
    int nt = blockIdx.x * 8 + warp;     // 0..511
    int kc = blockIdx.y;                // 0..1
    int par = s & 1;                    // h_prev frag parity

    float d[2][4];
#pragma unroll
    for (int mt = 0; mt < 2; mt++)
#pragma unroll
        for (int q = 0; q < 4; q++) d[mt][q] = 0.0f;

    const uint4* lw = g_lw + ((size_t)nt * UTL + kc * KCQ) * 32 + lane;
#pragma unroll 2
    for (int u = 0; u < KCQ; u++) {
        int ut = kc * KCQ + u;
        const uint4 *bH, *bL;
        if (ut < 16)      { bH = g_embfH  + (ut * 2) * 32;        bL = g_embfL  + (ut * 2) * 32; }
        else if (ut < 48) { bH = g_featfH + ((ut - 16) * 2) * 32; bL = g_featfL + ((ut - 16) * 2) * 32; }
        else              { bH = g_hfH[par] + ((ut - 48) * 2) * 32; bL = g_hfL[par] + ((ut - 48) * 2) * 32; }
        uint4 ah0 = bH[lane];
        uint4 ah1 = bH[32 + lane];
        uint4 al0 = bL[lane];
        uint4 al1 = bL[32 + lane];
        uint4 wb = lw[(size_t)u * 32];
        mma16816(d[0], ah0.x, ah0.y, ah0.z, ah0.w, wb.x, wb.y);  // hi*hi
        mma16816(d[0], ah0.x, ah0.y, ah0.z, ah0.w, wb.z, wb.w);  // hi*lo
        mma16816(d[0], al0.x, al0.y, al0.z, al0.w, wb.x, wb.y);  // lo*hi
        mma16816(d[1], ah1.x, ah1.y, ah1.z, ah1.w, wb.x, wb.y);
        mma16816(d[1], ah1.x, ah1.y, ah1.z, ah1.w, wb.z, wb.w);
        mma16816(d[1], al1.x, al1.y, al1.z, al1.w, wb.x, wb.y);
    }

    int g = lane >> 2, t = lane & 3;
#pragma unroll
    for (int mt = 0; mt < 2; mt++) {
#pragma unroll
        for (int row = 0; row < 2; row++) {
            int b = mt * 16 + g + row * 8;
            float* zp = g_zpart + (size_t)kc * NB * NJ + b * NJ + nt * 8 + t * 2;
            zp[0] = d[mt][row * 2 + 0];
            zp[1] = d[mt][row * 2 + 1];
        }
    }
}

// ---------------- LSTM combine: partials -> gates -> h-fragments ----------
__global__ void lstm_combine_kernel(const float* __restrict__ bias, int s) {
    int idx = blockIdx.x * 256 + threadIdx.x;   // 0..32767
    int b = idx >> 10;
    int j = idx & 1023;
    float z0 = bias[j], z1 = bias[NU + j], z2 = bias[2 * NU + j], z3 = bias[3 * NU + j];
#pragma unroll
    for (int kc = 0; kc < 2; kc++) {
        const float* zp = g_zpart + (size_t)kc * NB * NJ + b * NJ;
        z0 += zp[j];
        z1 += zp[NU + j];
        z2 += zp[2 * NU + j];
        z3 += zp[3 * NU + j];
    }
    float ig = 1.0f / (1.0f + expf(-z0));
    float fg = 1.0f / (1.0f + expf(-z1));
    float og = 1.0f / (1.0f + expf(-z3));
    float cold = g_c[b * NU + j];
    float cn = fg * cold + ig * tanhf(z2);
    float hn = og * tanhf(cn);
    g_c[b * NU + j] = cn;

    // write h directly as bf16(hi,lo) A-fragment elements
    int p = (s & 1) ^ 1;
    int mt = b >> 4, ml = b & 15;
    int g = ml & 7, rr = ml >> 3;
    int ut = j >> 4, kl = j & 15;
    int t = (kl & 7) >> 1, half = kl & 1, rhi = (kl >= 8);
    int lane = g * 4 + t;
    int reg = rr + rhi * 2;
    __nv_bfloat16 hi, lo;
    split_bf16(hn, hi, lo);
    int o = (ut * 2 + mt) * 32 + lane;
    reinterpret_cast<unsigned short*>(&g_hfH[p][o])[reg * 2 + half] =
        *reinterpret_cast<unsigned short*>(&hi);
    reinterpret_cast<unsigned short*>(&g_hfL[p][o])[reg * 2 + half] =
        *reinterpret_cast<unsigned short*>(&lo);
}

// ---------------- logits via tensor-core mma ----------------
__global__ void __launch_bounds__(256, 2)
logits_mma_kernel(const float* __restrict__ pb, int s) {
    __shared__ unsigned long long sbest[NB];
    int tid = threadIdx.x;
    int warp = tid >> 5;
    int lane = tid & 31;
    int g = lane >> 2, t = lane & 3;
    int p = (s & 1) ^ 1;
    if (tid < NB) sbest[tid] = 0ULL;
    __syncthreads();

    int vbase = blockIdx.x * 128 + warp * 16;
    int vt0 = vbase >> 3;

    float d[2][2][4];
#pragma unroll
    for (int mt = 0; mt < 2; mt++)
#pragma unroll
        for (int nt = 0; nt < 2; nt++)
#pragma unroll
            for (int q = 0; q < 4; q++) d[mt][nt][q] = 0.0f;

    const uint4* HH = g_hfH[p];
    const uint4* LL = g_hfL[p];
    const uint4* wp0 = &g_wpack[((size_t)vt0 * 64) * 32 + lane];
    const uint4* wp1 = &g_wpack[((size_t)(vt0 + 1) * 64) * 32 + lane];
#pragma unroll 2
    for (int ut = 0; ut < 64; ut++) {
        uint4 ah0 = __ldg(&HH[(ut * 2 + 0) * 32 + lane]);
        uint4 ah1 = __ldg(&HH[(ut * 2 + 1) * 32 + lane]);
        uint4 al0 = __ldg(&LL[(ut * 2 + 0) * 32 + lane]);
        uint4 al1 = __ldg(&LL[(ut * 2 + 1) * 32 + lane]);
        uint4 wb0 = __ldg(wp0 + (size_t)ut * 32);
        uint4 wb1 = __ldg(wp1 + (size_t)ut * 32);
        mma16816(d[0][0], ah0.x, ah0.y, ah0.z, ah0.w, wb0.x, wb0.y);
        mma16816(d[0][0], ah0.x, ah0.y, ah0.z, ah0.w, wb0.z, wb0.w);
        mma16816(d[0][0], al0.x, al0.y, al0.z, al0.w, wb0.x, wb0.y);
        mma16816(d[1][0], ah1.x, ah1.y, ah1.z, ah1.w, wb0.x, wb0.y);
        mma16816(d[1][0], ah1.x, ah1.y, ah1.z, ah1.w, wb0.z, wb0.w);
        mma16816(d[1][0], al1.x, al1.y, al1.z, al1.w, wb0.x, wb0.y);
        mma16816(d[0][1], ah0.x, ah0.y, ah0.z, ah0.w, wb1.x, wb1.y);
        mma16816(d[0][1], ah0.x, ah0.y, ah0.z, ah0.w, wb1.z, wb1.w);
        mma16816(d[0][1], al0.x, al0.y, al0.z, al0.w, wb1.x, wb1.y);
        mma16816(d[1][1], ah1.x, ah1.y, ah1.z, ah1.w, wb1.x, wb1.y);
        mma16816(d[1][1], ah1.x, ah1.y, ah1.z, ah1.w, wb1.z, wb1.w);
        mma16816(d[1][1], al1.x, al1.y, al1.z, al1.w, wb1.x, wb1.y);
    }

    int v0 = vbase + t * 2;
    int v2 = vbase + 8 + t * 2;
    float pb0 = pb[v0], pb1 = pb[v0 + 1], pb2 = pb[v2], pb3 = pb[v2 + 1];
    uint2 sk = g_subkey[s];
    int par = s & 1;

#pragma unroll
    for (int mt = 0; mt < 2; mt++) {
#pragma unroll
        for (int row = 0; row < 2; row++) {
            int b = mt * 16 + g + row * 8;
            uint32_t base = (uint32_t)(b * NV);
            float x0 = d[mt][0][row * 2 + 0] + pb0 + gumbel_from_bits(jax_bits(sk, base + v0));
            float x1 = d[mt][0][row * 2 + 1] + pb1 + gumbel_from_bits(jax_bits(sk, base + v0 + 1));
            float x2 = d[mt][1][row * 2 + 0] + pb2 + gumbel_from_bits(jax_bits(sk, base + v2));
            float x3 = d[mt][1][row * 2 + 1] + pb3 + gumbel_from_bits(jax_bits(sk, base + v2 + 1));
            unsigned long long pk = pack_cand(x0, v0);
            unsigned long long p1 = pack_cand(x1, v0 + 1);
            unsigned long long p2 = pack_cand(x2, v2);
            unsigned long long p3 = pack_cand(x3, v2 + 1);
            if (p1 > pk) pk = p1;
            if (p2 > pk) pk = p2;
            if (p3 > pk) pk = p3;
            unsigned long long o;
            o = __shfl_xor_sync(0xffffffffu, pk, 1); if (o > pk) pk = o;
            o = __shfl_xor_sync(0xffffffffu, pk, 2); if (o > pk) pk = o;
            if (t == 0) atomicMax(&sbest[b], pk);
        }
    }
    __syncthreads();
    if (tid < NB) atomicMax(&g_best[par][tid], sbest[tid]);
}

// ---------------- finalize + emb-fragment pack (one 1024-thread block) -----
__global__ void finpack_kernel(const float* __restrict__ emb,
                               float* __restrict__ out, int s) {
    __shared__ int stok[NB];
    int tid = threadIdx.x;
    if (tid < NB) {
        if (s >= 0) {
            unsigned long long pk = g_best[s & 1][tid];
            int v = (int)(~(unsigned int)pk);
            out[tid * NSTEPS + s] = (float)v;
            g_best[(s & 1) ^ 1][tid] = 0ULL;
            stok[tid] = v;
        } else {
            stok[tid] = 1;   // START_TOKEN
        }
    }
    __syncthreads();

    int lane = tid & 31;
    int fi = tid >> 5;           // 0..31
    int mt = fi & 1;
    int ut = fi >> 1;            // 0..15
    int g = lane >> 2, t = lane & 3;
    int m0 = mt * 16 + g, m1 = m0 + 8;
    int k0 = ut * 16 + t * 2;
    const float* e0 = emb + (size_t)stok[m0] * NEMB;
    const float* e1 = emb + (size_t)stok[m1] * NEMB;
    float v00 = e0[k0],     v01 = e0[k0 + 1];
    float v10 = e1[k0],     v11 = e1[k0 + 1];
    float v20 = e0[k0 + 8], v21 = e0[k0 + 9];
    float v30 = e1[k0 + 8], v31 = e1[k0 + 9];
    __nv_bfloat16 h00,l00,h01,l01,h10,l10,h11,l11,h20,l20,h21,l21,h30,l30,h31,l31;
    split_bf16(v00,h00,l00); split_bf16(v01,h01,l01);
    split_bf16(v10,h10,l10); split_bf16(v11,h11,l11);
    split_bf16(v20,h20,l20); split_bf16(v21,h21,l21);
    split_bf16(v30,h30,l30); split_bf16(v31,h31,l31);
    int o = (ut * 2 + mt) * 32 + lane;
    g_embfH[o] = make_uint4(pack_bf2(h00,h01), pack_bf2(h10,h11),
                            pack_bf2(h20,h21), pack_bf2(h30,h31));
    g_embfL[o] = make_uint4(pack_bf2(l00,l01), pack_bf2(l10,l11),
                            pack_bf2(l20,l21), pack_bf2(l30,l31));
}

// ---------------- launch ----------------
extern "C" void kernel_launch(void* const* d_in, const int* in_sizes, int n_in,
                              void* d_out, int out_size) {
    bool el_mode = false, byte_mode = false;
    for (int i = 0; i < n_in; i++) {
        if (in_sizes[i] == 32000)  el_mode   = true;
        if (in_sizes[i] == 128000) byte_mode = true;
    }
    const float* img  = (const float*)d_in[0];
    const float* emb  = (const float*)d_in[1];
    const float* Kw   = (const float*)d_in[2];
    const float* Rw   = (const float*)d_in[3];
    const float* bias = (const float*)d_in[4];
    const float* W    = (const float*)d_in[5];
    const float* pb   = (const float*)d_in[6];
    if (el_mode) {
        for (int i = 0; i < n_in; i++) {
            const float* p = (const float*)d_in[i];
            switch (in_sizes[i]) {
                case 3276800:  img  = p; break;
                case 8192000:  emb  = p; break;
                case 3145728:  Kw   = p; break;
                case 4194304:  Rw   = p; break;
                case 4096:     bias = p; break;
                case 32768000: W    = p; break;
                case 32000:    pb   = p; break;
                default: break;
            }
        }
    } else if (byte_mode) {
        for (int i = 0; i < n_in; i++) {
            const float* p = (const float*)d_in[i];
            switch (in_sizes[i]) {
                case 13107200:  img  = p; break;
                case 32768000:  emb  = p; break;
                case 12582912:  Kw   = p; break;
                case 16777216:  Rw   = p; break;
                case 16384:     bias = p; break;
                case 131072000: W    = p; break;
                case 128000:    pb   = p; break;
                default: break;
            }
        }
    }
    float* out = (float*)d_out;

    init_kernel<<<64, 256>>>();
    feat_kernel<<<64, 256>>>(img);
    featpack_kernel<<<8, 256>>>();
    wpack_kernel<<<32000, 256>>>(W);
    lwpack_kernel<<<7168, 256>>>(Kw, Rw);
    finpack_kernel<<<1, 1024>>>(emb, out, -1);
    for (int s = 0; s < NSTEPS; s++) {
        lstm_mma_kernel<<<dim3(64, 2), 256>>>(s);
        lstm_combine_kernel<<<128, 256>>>(bias, s);
        logits_mma_kernel<<<250, 256>>>(pb, s);
        finpack_kernel<<<1, 1024>>>(emb, out, s);
    }
}